// round 5
// baseline (speedup 1.0000x reference)
#include <cuda_runtime.h>
#include <math.h>

#define IN_F   512
#define HID    256
#define BATCH  1024

// Column-major (transposed) edge masks: bit o of column i = edge (o,i) selected.
__device__ unsigned int g_cmask0[IN_F * (HID / 32)];   // [512][8]  layer 0
__device__ unsigned int g_cmask1[HID  * (IN_F / 32)];  // [256][16] layer 1

// ---------------------------------------------------------------------------
// Kernel 1: build TRANSPOSED bitmasks. One block = one 32(o) x 32(i) tile.
// Coalesced float2 reads, pred -> shared byte tile -> column ballot.
// Layer 0 tiles: 8 x 16 = 128 blocks; layer 1: 16 x 8 = 128 blocks.
// ---------------------------------------------------------------------------
__global__ __launch_bounds__(1024)
void mask_kernel(const float* __restrict__ logits0, const float* __restrict__ u0,
                 const float* __restrict__ logits1, const float* __restrict__ u1)
{
    __shared__ unsigned char tile[32][33];

    const int ty   = threadIdx.x >> 5;   // local o
    const int lane = threadIdx.x & 31;   // local i
    int bl = blockIdx.x;

    const float* L; const float* U; unsigned* CM;
    int to, ti, IN, cstride;
    if (bl < 128) {         // layer 0: o in [0,256), i in [0,512)
        L = logits0; U = u0; CM = g_cmask0;
        to = bl >> 4; ti = bl & 15; IN = IN_F; cstride = HID / 32;   // 8
    } else {                // layer 1: o in [0,512), i in [0,256)
        bl -= 128;
        L = logits1; U = u1; CM = g_cmask1;
        to = bl >> 3; ti = bl & 7;  IN = HID;  cstride = IN_F / 32;  // 16
    }

    int o = to * 32 + ty;
    int i = ti * 32 + lane;
    int e = o * IN + i;                       // float2 index (E=2)

    float2 l = reinterpret_cast<const float2*>(L)[e];
    float2 u = reinterpret_cast<const float2*>(U)[e];

    const float LO = 1e-10f;
    const float HI = 1.0f - 1e-10f;
    float ca = fminf(fmaxf(u.x, LO), HI);
    float cb = fminf(fmaxf(u.y, LO), HI);

    bool pred;
    if (l.x == l.y) {
        pred = cb > ca;                       // gumbel monotone in clipped u
    } else {
        float g0 = -logf(-logf(ca));
        float g1 = -logf(-logf(cb));
        pred = (l.y + g1) > (l.x + g0);
    }

    tile[ty][lane] = pred ? 1 : 0;
    __syncthreads();

    // warp ty emits column (local i = ty): bit (o-local = lane)
    unsigned bit = tile[lane][ty];
    unsigned bal = __ballot_sync(0xFFFFFFFFu, bit != 0);
    if (lane == 0) CM[(ti * 32 + ty) * cstride + to] = bal;
}

// ---------------------------------------------------------------------------
// Kernel 2: fused two-layer evaluation, one block per batch row.
// Column-walk algorithm: sort values, then walk the sorted order ONCE
// block-uniformly; each step broadcasts one mask column, thread t tests its
// bit. First set bit -> value; same-bucket extra hits -> fmin/fmax (exact).
// Expected walk length = max over outputs of Geom(1/2) ~ 12-16 steps.
// ---------------------------------------------------------------------------
__global__ __launch_bounds__(256)
void row_kernel(const float* __restrict__ x, float* __restrict__ out)
{
    __shared__ unsigned cnt[IN_F];    // counts, then exclusive offsets
    __shared__ unsigned skey[IN_F];   // sorted keys: (bucket<<9)|idx
    __shared__ float    sval[IN_F];   // exact x row
    __shared__ float    shv[HID];     // exact h row
    __shared__ unsigned wsum[8];

    const int b    = blockIdx.x;
    const int t    = threadIdx.x;     // 0..255
    const int lane = t & 31;
    const int w    = t >> 5;

    // ============ layer 0 sort: counting sort of x (512 linear buckets) ====
    cnt[t] = 0; cnt[t + 256] = 0;
    float v0 = x[b * IN_F + t];
    float v1 = x[b * IN_F + t + 256];
    sval[t] = v0; sval[t + 256] = v1;
    __syncthreads();

    int b0 = min((int)(v0 * 512.0f), 511);   // exact pow2 scaling -> monotone
    int b1 = min((int)(v1 * 512.0f), 511);
    unsigned r0 = atomicAdd(&cnt[b0], 1u);
    unsigned r1 = atomicAdd(&cnt[b1], 1u);
    __syncthreads();

    unsigned c0 = cnt[2 * t], c1 = cnt[2 * t + 1];
    unsigned s  = c0 + c1, sc = s;
#pragma unroll
    for (int d = 1; d < 32; d <<= 1) {
        unsigned o = __shfl_up_sync(0xFFFFFFFFu, sc, d);
        if (lane >= d) sc += o;
    }
    if (lane == 31) wsum[w] = sc;
    __syncthreads();
    unsigned wexcl = 0;
#pragma unroll
    for (int i = 0; i < 8; i++) if (i < w) wexcl += wsum[i];
    unsigned excl = wexcl + (sc - s);
    cnt[2 * t]     = excl;
    cnt[2 * t + 1] = excl + c0;
    __syncthreads();

    skey[cnt[b0] + r0] = ((unsigned)b0 << 9) | (unsigned)t;
    skey[cnt[b1] + r1] = ((unsigned)b1 << 9) | (unsigned)(t + 256);
    __syncthreads();

    // ============ layer 0 column walk: thread t owns hidden unit t =========
    float h = 1.0f;                   // default: no selected edge
    {
        bool done = false;
        unsigned qb = 0xFFFFFFFFu;
        for (int k = 0; k < IN_F; k++) {
            unsigned key = skey[k];                       // LDS broadcast
            unsigned i   = key & 511u;
            unsigned bk  = key >> 9;
            unsigned cm  = g_cmask0[i * 8 + w];           // warp-uniform LDG
            bool bit = (cm >> lane) & 1u;
            if (bit && (!done || bk == qb)) {
                float v = sval[i];
                if (!done) { h = v; qb = bk; done = true; }
                else        h = fminf(h, v);
            }
            if ((k & 3) == 3) {
                bool sat = done && (bk != qb);            // past my tie bucket
                if (__syncthreads_and(sat)) break;
            }
        }
    }
    __syncthreads();                  // walk done before smem reuse

    // ====== layer 1 sort: counting sort of h, LOG buckets, descending ======
    shv[t] = h;
    cnt[t] = 0;
    __syncthreads();

    // bucket = clamp((hbits>>19)-1792, 0, 255): exp + top-4 mantissa bits,
    // monotone in h >= 0; h <= 1.0 -> bucket <= 240.
    unsigned hb  = __float_as_uint(h);
    int bkt = min(max((int)(hb >> 19) - 1792, 0), 255);
    int bd  = 255 - bkt;              // descending
    unsigned rr = atomicAdd(&cnt[bd], 1u);
    __syncthreads();

    unsigned c = cnt[t], scn = c;
#pragma unroll
    for (int d = 1; d < 32; d <<= 1) {
        unsigned o = __shfl_up_sync(0xFFFFFFFFu, scn, d);
        if (lane >= d) scn += o;
    }
    if (lane == 31) wsum[w] = scn;
    __syncthreads();
    unsigned wex = 0;
#pragma unroll
    for (int i = 0; i < 8; i++) if (i < w) wex += wsum[i];
    cnt[t] = wex + scn - c;
    __syncthreads();

    skey[cnt[bd] + rr] = ((unsigned)bd << 9) | (unsigned)t;
    __syncthreads();

    // ====== layer 1 column walk: thread t owns outputs t and t+256 =========
    float ra = 0.0f, rb = 0.0f;       // default: no selected edge
    {
        bool da = false, db = false;
        unsigned qa = 0xFFFFFFFFu, qbb = 0xFFFFFFFFu;
        for (int k = 0; k < HID; k++) {
            unsigned key = skey[k];
            unsigned j   = key & 511u;
            unsigned bk  = key >> 9;
            unsigned cma = g_cmask1[j * 16 + w];          // bits for o = t
            unsigned cmb = g_cmask1[j * 16 + 8 + w];      // bits for o = t+256
            bool ba = (cma >> lane) & 1u;
            bool bb = (cmb >> lane) & 1u;
            float v = shv[j];
            if (ba && (!da || bk == qa)) {
                if (!da) { ra = v; qa = bk; da = true; } else ra = fmaxf(ra, v);
            }
            if (bb && (!db || bk == qbb)) {
                if (!db) { rb = v; qbb = bk; db = true; } else rb = fmaxf(rb, v);
            }
            if ((k & 3) == 3) {
                bool sat = (da && bk != qa) && (db && bk != qbb);
                if (__syncthreads_and(sat)) break;
            }
        }
    }

    out[b * IN_F + t]       = ra;
    out[b * IN_F + t + 256] = rb;
}

// ---------------------------------------------------------------------------
// kernel_launch: graph-capturable, allocation-free.
// Inputs: x, logits0, u0, logits1, u1. Output: float32 [1024,512].
// ---------------------------------------------------------------------------
extern "C" void kernel_launch(void* const* d_in, const int* in_sizes, int n_in,
                              void* d_out, int out_size)
{
    const float* x       = (const float*)d_in[0];
    const float* logits0 = (const float*)d_in[1];
    const float* u0      = (const float*)d_in[2];
    const float* logits1 = (const float*)d_in[3];
    const float* u1      = (const float*)d_in[4];
    float* out = (float*)d_out;

    mask_kernel<<<256, 1024>>>(logits0, u0, logits1, u1);
    row_kernel<<<BATCH, 256>>>(x, out);
}

// round 6
// speedup vs baseline: 1.6633x; 1.6633x over previous
#include <cuda_runtime.h>
#include <math.h>

#define IN_F   512
#define HID    256
#define BATCH  1024

// Column-major (transposed) edge masks: bit o of column i = edge (o,i) selected.
__device__ unsigned int g_cmask0[IN_F * (HID / 32)];   // [512][8]  layer 0
__device__ unsigned int g_cmask1[HID  * (IN_F / 32)];  // [256][16] layer 1

// ---------------------------------------------------------------------------
// Kernel 1: build TRANSPOSED bitmasks. One block = one 32(o) x 32(i) tile.
// ---------------------------------------------------------------------------
__global__ __launch_bounds__(1024)
void mask_kernel(const float* __restrict__ logits0, const float* __restrict__ u0,
                 const float* __restrict__ logits1, const float* __restrict__ u1)
{
    __shared__ unsigned char tile[32][33];

    const int ty   = threadIdx.x >> 5;   // local o
    const int lane = threadIdx.x & 31;   // local i
    int bl = blockIdx.x;

    const float* L; const float* U; unsigned* CM;
    int to, ti, IN, cstride;
    if (bl < 128) {         // layer 0: o in [0,256), i in [0,512)
        L = logits0; U = u0; CM = g_cmask0;
        to = bl >> 4; ti = bl & 15; IN = IN_F; cstride = HID / 32;   // 8
    } else {                // layer 1: o in [0,512), i in [0,256)
        bl -= 128;
        L = logits1; U = u1; CM = g_cmask1;
        to = bl >> 3; ti = bl & 7;  IN = HID;  cstride = IN_F / 32;  // 16
    }

    int o = to * 32 + ty;
    int i = ti * 32 + lane;
    int e = o * IN + i;                       // float2 index (E=2)

    float2 l = reinterpret_cast<const float2*>(L)[e];
    float2 u = reinterpret_cast<const float2*>(U)[e];

    const float LO = 1e-10f;
    const float HI = 1.0f - 1e-10f;
    float ca = fminf(fmaxf(u.x, LO), HI);
    float cb = fminf(fmaxf(u.y, LO), HI);

    bool pred;
    if (l.x == l.y) {
        pred = cb > ca;                       // gumbel monotone in clipped u
    } else {
        float g0 = -logf(-logf(ca));
        float g1 = -logf(-logf(cb));
        pred = (l.y + g1) > (l.x + g0);
    }

    tile[ty][lane] = pred ? 1 : 0;
    __syncthreads();

    unsigned bit = tile[lane][ty];
    unsigned bal = __ballot_sync(0xFFFFFFFFu, bit != 0);
    if (lane == 0) CM[(ti * 32 + ty) * cstride + to] = bal;
}

// ---------------------------------------------------------------------------
// 32x32 bit-matrix transpose across a warp (5 shfl_xor butterfly steps).
// In:  lane r holds bits over columns c.  Out: lane c holds bits over rows r.
// ---------------------------------------------------------------------------
__device__ __forceinline__ unsigned warp_bit_transpose(unsigned x, int lane)
{
#pragma unroll
    for (int j = 16; j >= 1; j >>= 1) {
        unsigned mk = 0xFFFFFFFFu / ((1u << j) + 1u);  // constant-folded
        unsigned y  = __shfl_xor_sync(0xFFFFFFFFu, x, j);
        x = (lane & j) ? ((x & ~mk) | ((y >> j) & mk))
                       : ((x &  mk) | ((y & mk) << j));
    }
    return x;
}

// ---------------------------------------------------------------------------
// Kernel 2: fused two-layer evaluation, one block per batch row.
// Sort values (counting sort), then warp-local BIT-PARALLEL walk:
// each warp owns one 32-output mask word; per 32-position window each lane
// loads one mask column, a warp bit-transpose gives each lane (=output) its
// hit bits over sorted positions -> __ffs = first hit. Tie buckets rescanned
// exactly (fmin/fmax over same-bucket hits, spill across windows handled).
// ---------------------------------------------------------------------------
__global__ __launch_bounds__(256)
void row_kernel(const float* __restrict__ x, float* __restrict__ out)
{
    __shared__ unsigned cnt[IN_F];    // counts, then exclusive offsets
    __shared__ unsigned skey[IN_F];   // sorted keys: (bucket<<9)|idx
    __shared__ float    sval[IN_F];   // exact x row
    __shared__ float    shv[HID];     // exact h row
    __shared__ unsigned wsum[8];

    const int b    = blockIdx.x;
    const int t    = threadIdx.x;     // 0..255
    const int lane = t & 31;
    const int w    = t >> 5;

    // ============ layer 0 sort: counting sort of x (512 linear buckets) ====
    cnt[t] = 0; cnt[t + 256] = 0;
    float v0 = x[b * IN_F + t];
    float v1 = x[b * IN_F + t + 256];
    sval[t] = v0; sval[t + 256] = v1;
    __syncthreads();

    int b0 = min((int)(v0 * 512.0f), 511);   // exact pow2 scaling -> monotone
    int b1 = min((int)(v1 * 512.0f), 511);
    unsigned r0 = atomicAdd(&cnt[b0], 1u);
    unsigned r1 = atomicAdd(&cnt[b1], 1u);
    __syncthreads();

    unsigned c0 = cnt[2 * t], c1 = cnt[2 * t + 1];
    unsigned s  = c0 + c1, sc = s;
#pragma unroll
    for (int d = 1; d < 32; d <<= 1) {
        unsigned o = __shfl_up_sync(0xFFFFFFFFu, sc, d);
        if (lane >= d) sc += o;
    }
    if (lane == 31) wsum[w] = sc;
    __syncthreads();
    unsigned wexcl = 0;
#pragma unroll
    for (int i = 0; i < 8; i++) if (i < w) wexcl += wsum[i];
    unsigned excl = wexcl + (sc - s);
    cnt[2 * t]     = excl;
    cnt[2 * t + 1] = excl + c0;
    __syncthreads();

    skey[cnt[b0] + r0] = ((unsigned)b0 << 9) | (unsigned)t;
    skey[cnt[b1] + r1] = ((unsigned)b1 << 9) | (unsigned)(t + 256);
    __syncthreads();

    // ===== layer 0 bit-parallel walk: warp w owns outputs 32w..32w+31 ======
    float h = 1.0f;                   // default: no selected edge
    {
        bool done = false, pend = false;
        unsigned qb = 0;
        for (int base = 0; base < IN_F; base += 32) {
            unsigned keyl = skey[base + lane];
            unsigned col  = g_cmask0[(keyl & 511u) * 8 + w];
            unsigned hits = warp_bit_transpose(col, lane);
            unsigned lastb = skey[base + 31] >> 9;

            unsigned scanb = 0;
            if (!done) {
                if (hits) {
                    int p = __ffs(hits) - 1;
                    unsigned k0 = skey[base + p];
                    qb = k0 >> 9;
                    h  = sval[k0 & 511u];
                    done = true; pend = true;
                    scanb = hits & (0xFFFFFFFEu << p);   // bits strictly > p
                }
            } else if (pend) {
                scanb = hits;
            }
            while (scanb) {                               // same-bucket rescan
                int p2 = __ffs(scanb) - 1;
                scanb &= scanb - 1;
                unsigned k2 = skey[base + p2];
                if ((k2 >> 9) != qb) { pend = false; break; }
                h = fminf(h, sval[k2 & 511u]);
            }
            if (pend) pend = (lastb == qb);               // bucket spills on?
            if (__all_sync(0xFFFFFFFFu, done && !pend)) break;
        }
    }
    __syncthreads();                  // all walks read skey/sval before reuse

    // ====== layer 1 sort: counting sort of h, LOG buckets, descending ======
    shv[t] = h;
    cnt[t] = 0;
    __syncthreads();

    // bucket = clamp((hbits>>19)-1792, 0, 255): exp + top-4 mantissa bits,
    // monotone in h >= 0; h <= 1.0 -> bucket <= 240.
    unsigned hb  = __float_as_uint(h);
    int bkt = min(max((int)(hb >> 19) - 1792, 0), 255);
    int bd  = 255 - bkt;              // descending
    unsigned rr = atomicAdd(&cnt[bd], 1u);
    __syncthreads();

    unsigned c = cnt[t], scn = c;
#pragma unroll
    for (int d = 1; d < 32; d <<= 1) {
        unsigned o = __shfl_up_sync(0xFFFFFFFFu, scn, d);
        if (lane >= d) scn += o;
    }
    if (lane == 31) wsum[w] = scn;
    __syncthreads();
    unsigned wex = 0;
#pragma unroll
    for (int i = 0; i < 8; i++) if (i < w) wex += wsum[i];
    cnt[t] = wex + scn - c;
    __syncthreads();

    skey[cnt[bd] + rr] = ((unsigned)bd << 9) | (unsigned)t;
    __syncthreads();

    // == layer 1 bit-parallel walk: warp w owns words w (o=t) and w+8 (t+256)
    float ra = 0.0f, rb = 0.0f;       // default: no selected edge
    {
        bool da = false, pa = false, db = false, pb = false;
        unsigned qa = 0, qv = 0;
        for (int base = 0; base < HID; base += 32) {
            unsigned keyl = skey[base + lane];
            unsigned j    = keyl & 511u;
            unsigned ca_  = g_cmask1[j * 16 + w];
            unsigned cb_  = g_cmask1[j * 16 + 8 + w];
            unsigned hta  = warp_bit_transpose(ca_, lane);
            unsigned htb  = warp_bit_transpose(cb_, lane);
            unsigned lastb = skey[base + 31] >> 9;

            // word a
            unsigned sa = 0;
            if (!da) {
                if (hta) {
                    int p = __ffs(hta) - 1;
                    unsigned k0 = skey[base + p];
                    qa = k0 >> 9; ra = shv[k0 & 511u];
                    da = true; pa = true;
                    sa = hta & (0xFFFFFFFEu << p);
                }
            } else if (pa) sa = hta;
            while (sa) {
                int p2 = __ffs(sa) - 1; sa &= sa - 1;
                unsigned k2 = skey[base + p2];
                if ((k2 >> 9) != qa) { pa = false; break; }
                ra = fmaxf(ra, shv[k2 & 511u]);
            }
            if (pa) pa = (lastb == qa);

            // word b
            unsigned sb = 0;
            if (!db) {
                if (htb) {
                    int p = __ffs(htb) - 1;
                    unsigned k0 = skey[base + p];
                    qv = k0 >> 9; rb = shv[k0 & 511u];
                    db = true; pb = true;
                    sb = htb & (0xFFFFFFFEu << p);
                }
            } else if (pb) sb = htb;
            while (sb) {
                int p2 = __ffs(sb) - 1; sb &= sb - 1;
                unsigned k2 = skey[base + p2];
                if ((k2 >> 9) != qv) { pb = false; break; }
                rb = fmaxf(rb, shv[k2 & 511u]);
            }
            if (pb) pb = (lastb == qv);

            if (__all_sync(0xFFFFFFFFu, da && !pa && db && !pb)) break;
        }
    }

    out[b * IN_F + t]       = ra;
    out[b * IN_F + t + 256] = rb;
}

// ---------------------------------------------------------------------------
// kernel_launch: graph-capturable, allocation-free.
// Inputs: x, logits0, u0, logits1, u1. Output: float32 [1024,512].
// ---------------------------------------------------------------------------
extern "C" void kernel_launch(void* const* d_in, const int* in_sizes, int n_in,
                              void* d_out, int out_size)
{
    const float* x       = (const float*)d_in[0];
    const float* logits0 = (const float*)d_in[1];
    const float* u0      = (const float*)d_in[2];
    const float* logits1 = (const float*)d_in[3];
    const float* u1      = (const float*)d_in[4];
    float* out = (float*)d_out;

    mask_kernel<<<256, 1024>>>(logits0, u0, logits1, u1);
    row_kernel<<<BATCH, 256>>>(x, out);
}